// round 5
// baseline (speedup 1.0000x reference)
#include <cuda_runtime.h>

#define Bn  2
#define Tn  2048
#define Dn  1024
#define Hn  16
#define DKn 64
#define Mn  (Bn*Tn)   // 4096
#define Nqkv (3*Dn)   // 3072

// Scratch (device globals — no allocations allowed)
__device__ float g_Q[Bn*Hn*Tn*DKn];   // [B,H,T,DK], pre-scaled by 1/8
__device__ float g_K[Bn*Hn*Tn*DKn];
__device__ float g_V[Bn*Hn*Tn*DKn];
__device__ float g_A[Bn*Tn*Dn];       // attention output [B,T,D]

// ---------------------------------------------------------------------------
// tf32 helpers
// ---------------------------------------------------------------------------
__device__ __forceinline__ unsigned f2tf32(float x) {
    unsigned r;
    asm("cvt.rna.tf32.f32 %0, %1;" : "=r"(r) : "f"(x));
    return r;
}

__device__ __forceinline__ void mma_tf32(float* c, const unsigned* a,
                                         unsigned b0, unsigned b1) {
    asm volatile(
        "mma.sync.aligned.m16n8k8.row.col.f32.tf32.tf32.f32 "
        "{%0,%1,%2,%3}, {%4,%5,%6,%7}, {%8,%9}, {%0,%1,%2,%3};\n"
        : "+f"(c[0]), "+f"(c[1]), "+f"(c[2]), "+f"(c[3])
        : "r"(a[0]), "r"(a[1]), "r"(a[2]), "r"(a[3]), "r"(b0), "r"(b1));
}

// ---------------------------------------------------------------------------
// 2-stage pipelined GEMM mainloop:
//   acc[128x128] += A[m0:+128, :] @ B[n0:+128, :]^T   (K = Dn, k-tile 32)
// Dynamic smem: stage s at sm + s*9216 ; A at +0 (128x36), W at +4608.
// Per iteration: LDG(k+1) -> mma(k) -> STS(k+1 into other stage) -> 1 bar.
// ---------------------------------------------------------------------------
#define GEMM_SM_WORDS (2 * 2 * 128 * 36)      // 18432 words = 73728 B
#define GEMM_SM_BYTES (GEMM_SM_WORDS * 4)

__device__ __forceinline__ void gemm_pipe(
    const float* __restrict__ Ap, const float* __restrict__ Bp,
    unsigned* sm, int m0, int n0, int tid, int lane, int wm, int wn,
    float acc[2][8][4])
{
    const int arow = tid >> 3;
    const int acol = (tid & 7) * 4;
    const int ar0  = wm * 32 + (lane >> 2);
    const int l3   = lane & 3;
    const int nb   = wn * 64 + (lane >> 2);

    float4 av[4], wv[4];

    // Prologue: tile 0 -> stage 0
    #pragma unroll
    for (int s = 0; s < 4; s++) {
        int r = arow + 32 * s;
        av[s] = *(const float4*)&Ap[(m0 + r) * Dn + acol];
        wv[s] = *(const float4*)&Bp[(n0 + r) * Dn + acol];
    }
    #pragma unroll
    for (int s = 0; s < 4; s++) {
        int r = arow + 32 * s;
        unsigned* pa = &sm[r * 36 + acol];
        pa[0] = f2tf32(av[s].x); pa[1] = f2tf32(av[s].y);
        pa[2] = f2tf32(av[s].z); pa[3] = f2tf32(av[s].w);
        unsigned* pw = &sm[4608 + r * 36 + acol];
        pw[0] = f2tf32(wv[s].x); pw[1] = f2tf32(wv[s].y);
        pw[2] = f2tf32(wv[s].z); pw[3] = f2tf32(wv[s].w);
    }
    __syncthreads();

    for (int kt = 0; kt < Dn / 32; kt++) {
        unsigned* curA = sm + (kt & 1) * 9216;
        unsigned* curW = curA + 4608;
        const bool more = (kt + 1 < Dn / 32);

        // Prefetch next k-tile into registers (overlaps the mma burst)
        if (more) {
            const int k0 = (kt + 1) * 32;
            #pragma unroll
            for (int s = 0; s < 4; s++) {
                int r = arow + 32 * s;
                av[s] = *(const float4*)&Ap[(m0 + r) * Dn + k0 + acol];
                wv[s] = *(const float4*)&Bp[(n0 + r) * Dn + k0 + acol];
            }
        }

        // mma burst on current stage
        #pragma unroll
        for (int ks = 0; ks < 32; ks += 8) {
            unsigned afr[2][4];
            #pragma unroll
            for (int mt = 0; mt < 2; mt++) {
                int r = ar0 + mt * 16;
                afr[mt][0] = curA[r * 36 + ks + l3];
                afr[mt][1] = curA[(r + 8) * 36 + ks + l3];
                afr[mt][2] = curA[r * 36 + ks + l3 + 4];
                afr[mt][3] = curA[(r + 8) * 36 + ks + l3 + 4];
            }
            #pragma unroll
            for (int j = 0; j < 8; j++) {
                int n = nb + j * 8;
                unsigned b0 = curW[n * 36 + ks + l3];
                unsigned b1 = curW[n * 36 + ks + l3 + 4];
                mma_tf32(acc[0][j], afr[0], b0, b1);
                mma_tf32(acc[1][j], afr[1], b0, b1);
            }
        }

        // Store prefetched tile into the other stage (safe: all reads of that
        // stage finished before the barrier at the end of the previous iter)
        if (more) {
            unsigned* nA = sm + ((kt + 1) & 1) * 9216;
            unsigned* nW = nA + 4608;
            #pragma unroll
            for (int s = 0; s < 4; s++) {
                int r = arow + 32 * s;
                unsigned* pa = &nA[r * 36 + acol];
                pa[0] = f2tf32(av[s].x); pa[1] = f2tf32(av[s].y);
                pa[2] = f2tf32(av[s].z); pa[3] = f2tf32(av[s].w);
                unsigned* pw = &nW[r * 36 + acol];
                pw[0] = f2tf32(wv[s].x); pw[1] = f2tf32(wv[s].y);
                pw[2] = f2tf32(wv[s].z); pw[3] = f2tf32(wv[s].w);
            }
        }
        __syncthreads();
    }
}

// ---------------------------------------------------------------------------
// Kernel 1: QKV = x @ w_qkv^T + b_qkv, fused RoPE + 1/8 scale on q (tf32 mma)
// ---------------------------------------------------------------------------
__global__ __launch_bounds__(256, 2) void qkv_mma_kernel(
    const float* __restrict__ x, const float* __restrict__ w,
    const float* __restrict__ bias, const float* __restrict__ fc,
    const float* __restrict__ fs)
{
    extern __shared__ unsigned dynsm[];
    const int tid  = threadIdx.x;
    const int warp = tid >> 5, lane = tid & 31;
    const int wm = warp & 3, wn = warp >> 2;
    const int m0 = blockIdx.y * 128;
    const int n0 = blockIdx.x * 128;

    float acc[2][8][4];
    #pragma unroll
    for (int mt = 0; mt < 2; mt++)
        #pragma unroll
        for (int j = 0; j < 8; j++)
            #pragma unroll
            for (int e = 0; e < 4; e++) acc[mt][j][e] = 0.f;

    gemm_pipe(x, w, dynsm, m0, n0, tid, lane, wm, wn, acc);

    const int region = n0 >> 10;
    float* dst = (region == 0) ? g_Q : (region == 1) ? g_K : g_V;
    const int rbase = m0 + wm * 32 + (lane >> 2);

    #pragma unroll
    for (int j = 0; j < 8; j++) {
        const int n  = n0 + wn * 64 + j * 8 + (lane & 3) * 2;
        const int h  = (n & 1023) >> 6;
        const int d  = n & 63;
        const int p  = d >> 1;
        const float bv0 = bias[n], bv1 = bias[n + 1];
        #pragma unroll
        for (int mt = 0; mt < 2; mt++) {
            #pragma unroll
            for (int half = 0; half < 2; half++) {
                const int r  = rbase + mt * 16 + half * 8;
                const int bi = r >> 11;
                const int t  = r & 2047;
                float re = acc[mt][j][half * 2 + 0] + bv0;
                float im = acc[mt][j][half * 2 + 1] + bv1;
                if (region < 2) {
                    float c = fc[t * (DKn / 2) + p];
                    float s = fs[t * (DKn / 2) + p];
                    float nre = re * c - im * s;
                    float nim = re * s + im * c;
                    re = nre; im = nim;
                    if (region == 0) { re *= 0.125f; im *= 0.125f; }
                }
                *(float2*)&dst[((bi * Hn + h) * Tn + t) * DKn + d] =
                    make_float2(re, im);
            }
        }
    }
}

// ---------------------------------------------------------------------------
// Kernel 3: out = g_A @ w_out^T + b_out (tf32 mma)
// ---------------------------------------------------------------------------
__global__ __launch_bounds__(256, 2) void proj_mma_kernel(
    const float* __restrict__ w, const float* __restrict__ bias,
    float* __restrict__ out)
{
    extern __shared__ unsigned dynsm[];
    const int tid  = threadIdx.x;
    const int warp = tid >> 5, lane = tid & 31;
    const int wm = warp & 3, wn = warp >> 2;
    const int m0 = blockIdx.y * 128;
    const int n0 = blockIdx.x * 128;

    float acc[2][8][4];
    #pragma unroll
    for (int mt = 0; mt < 2; mt++)
        #pragma unroll
        for (int j = 0; j < 8; j++)
            #pragma unroll
            for (int e = 0; e < 4; e++) acc[mt][j][e] = 0.f;

    gemm_pipe(g_A, w, dynsm, m0, n0, tid, lane, wm, wn, acc);

    const int rbase = m0 + wm * 32 + (lane >> 2);
    #pragma unroll
    for (int j = 0; j < 8; j++) {
        const int n = n0 + wn * 64 + j * 8 + (lane & 3) * 2;
        const float bv0 = bias[n], bv1 = bias[n + 1];
        #pragma unroll
        for (int mt = 0; mt < 2; mt++) {
            #pragma unroll
            for (int half = 0; half < 2; half++) {
                const int r = rbase + mt * 16 + half * 8;
                *(float2*)&out[r * Dn + n] =
                    make_float2(acc[mt][j][half * 2 + 0] + bv0,
                                acc[mt][j][half * 2 + 1] + bv1);
            }
        }
    }
}

// ---------------------------------------------------------------------------
// Kernel 2: causal flash attention on tf32 tensor cores (unchanged, round 4)
// ---------------------------------------------------------------------------
#define KS_STRIDE 68
#define VS_STRIDE 72
#define ATT_SMEM_WORDS (64*KS_STRIDE + 64*VS_STRIDE)

__global__ __launch_bounds__(256) void attn_mma_kernel()
{
    __shared__ unsigned sm[ATT_SMEM_WORDS];
    unsigned* Ks = sm;
    unsigned* Vs = sm + 64 * KS_STRIDE;
    unsigned* Qs = sm;                    // staging alias

    const int tid  = threadIdx.x;
    const int warp = tid >> 5, lane = tid & 31;
    const int q    = lane >> 2, l3 = lane & 3;
    const int qblk = (int)gridDim.x - 1 - (int)blockIdx.x;
    const int bh   = blockIdx.y;
    const int q0   = qblk * 128;

    const float* Qg = g_Q + (bh * Tn + q0) * DKn;
    const float* Kg = g_K + bh * Tn * DKn;
    const float* Vg = g_V + bh * Tn * DKn;

    #pragma unroll
    for (int s = 0; s < 8; s++) {
        int idx = tid + 256 * s;
        int r = idx >> 4, c = (idx & 15) * 4;
        float4 v = *(const float4*)&Qg[r * DKn + c];
        *(uint4*)&Qs[r * KS_STRIDE + c] =
            make_uint4(f2tf32(v.x), f2tf32(v.y), f2tf32(v.z), f2tf32(v.w));
    }
    __syncthreads();

    unsigned Qf[8][4];
    const int wrow = warp * 16;
    #pragma unroll
    for (int j = 0; j < 8; j++) {
        int rb = (wrow + q) * KS_STRIDE + j * 8 + l3;
        Qf[j][0] = Qs[rb];
        Qf[j][1] = Qs[rb + 8 * KS_STRIDE];
        Qf[j][2] = Qs[rb + 4];
        Qf[j][3] = Qs[rb + 8 * KS_STRIDE + 4];
    }

    float O[8][4];
    #pragma unroll
    for (int j = 0; j < 8; j++)
        #pragma unroll
        for (int e = 0; e < 4; e++) O[j][e] = 0.f;
    float m_lo = -1e30f, m_hi = -1e30f, l_lo = 0.f, l_hi = 0.f;

    const int wr_lo = q0 + wrow;
    const int wr_hi = wr_lo + 15;
    const int src_lo = (lane & ~3) | (l3 >> 1);
    const int src_hi = src_lo + 2;
    const bool odd = (l3 & 1);
    const int n_kt = 2 * qblk + 2;

    for (int kt = 0; kt < n_kt; kt++) {
        const int k0 = kt * 64;
        __syncthreads();
        #pragma unroll
        for (int s = 0; s < 4; s++) {
            int idx = tid + 256 * s;
            int r = idx >> 4, c = (idx & 15) * 4;
            float4 kv = *(const float4*)&Kg[(k0 + r) * DKn + c];
            *(uint4*)&Ks[r * KS_STRIDE + c] =
                make_uint4(f2tf32(kv.x), f2tf32(kv.y), f2tf32(kv.z), f2tf32(kv.w));
            float4 vv = *(const float4*)&Vg[(k0 + r) * DKn + c];
            *(uint4*)&Vs[r * VS_STRIDE + c] =
                make_uint4(f2tf32(vv.x), f2tf32(vv.y), f2tf32(vv.z), f2tf32(vv.w));
        }
        __syncthreads();

        if (k0 > wr_hi) continue;

        float S[8][4];
        #pragma unroll
        for (int j = 0; j < 8; j++)
            #pragma unroll
            for (int e = 0; e < 4; e++) S[j][e] = 0.f;

        #pragma unroll
        for (int ks = 0; ks < 8; ks++) {
            #pragma unroll
            for (int j = 0; j < 8; j++) {
                unsigned b0 = Ks[(j * 8 + q) * KS_STRIDE + ks * 8 + l3];
                unsigned b1 = Ks[(j * 8 + q) * KS_STRIDE + ks * 8 + l3 + 4];
                mma_tf32(S[j], Qf[ks], b0, b1);
            }
        }

        if (k0 + 63 > wr_lo) {
            const int r0 = wr_lo + q;
            #pragma unroll
            for (int j = 0; j < 8; j++) {
                const int c = k0 + j * 8 + 2 * l3;
                if (c     > r0)     S[j][0] = -1e30f;
                if (c + 1 > r0)     S[j][1] = -1e30f;
                if (c     > r0 + 8) S[j][2] = -1e30f;
                if (c + 1 > r0 + 8) S[j][3] = -1e30f;
            }
        }

        float mx0 = -1e30f, mx1 = -1e30f;
        #pragma unroll
        for (int j = 0; j < 8; j++) {
            mx0 = fmaxf(mx0, fmaxf(S[j][0], S[j][1]));
            mx1 = fmaxf(mx1, fmaxf(S[j][2], S[j][3]));
        }
        mx0 = fmaxf(mx0, __shfl_xor_sync(0xffffffffu, mx0, 1));
        mx0 = fmaxf(mx0, __shfl_xor_sync(0xffffffffu, mx0, 2));
        mx1 = fmaxf(mx1, __shfl_xor_sync(0xffffffffu, mx1, 1));
        mx1 = fmaxf(mx1, __shfl_xor_sync(0xffffffffu, mx1, 2));

        const float mn0 = fmaxf(m_lo, mx0);
        const float mn1 = fmaxf(m_hi, mx1);
        const float a0  = __expf(m_lo - mn0);
        const float a1  = __expf(m_hi - mn1);
        m_lo = mn0; m_hi = mn1;

        float s0 = 0.f, s1 = 0.f;
        #pragma unroll
        for (int j = 0; j < 8; j++) {
            S[j][0] = __expf(S[j][0] - mn0);
            S[j][1] = __expf(S[j][1] - mn0);
            s0 += S[j][0] + S[j][1];
            S[j][2] = __expf(S[j][2] - mn1);
            S[j][3] = __expf(S[j][3] - mn1);
            s1 += S[j][2] + S[j][3];
        }
        s0 += __shfl_xor_sync(0xffffffffu, s0, 1);
        s0 += __shfl_xor_sync(0xffffffffu, s0, 2);
        s1 += __shfl_xor_sync(0xffffffffu, s1, 1);
        s1 += __shfl_xor_sync(0xffffffffu, s1, 2);
        l_lo = l_lo * a0 + s0;
        l_hi = l_hi * a1 + s1;

        #pragma unroll
        for (int j = 0; j < 8; j++) {
            O[j][0] *= a0; O[j][1] *= a0;
            O[j][2] *= a1; O[j][3] *= a1;
        }

        #pragma unroll
        for (int j = 0; j < 8; j++)
            #pragma unroll
            for (int e = 0; e < 4; e++)
                S[j][e] = __uint_as_float(f2tf32(S[j][e]));

        #pragma unroll
        for (int ks = 0; ks < 8; ks++) {
            unsigned A[4];
            {
                float x0 = __shfl_sync(0xffffffffu, S[ks][0], src_lo);
                float x1 = __shfl_sync(0xffffffffu, S[ks][1], src_lo);
                A[0] = __float_as_uint(odd ? x1 : x0);
                float y0 = __shfl_sync(0xffffffffu, S[ks][2], src_lo);
                float y1 = __shfl_sync(0xffffffffu, S[ks][3], src_lo);
                A[1] = __float_as_uint(odd ? y1 : y0);
                float z0 = __shfl_sync(0xffffffffu, S[ks][0], src_hi);
                float z1 = __shfl_sync(0xffffffffu, S[ks][1], src_hi);
                A[2] = __float_as_uint(odd ? z1 : z0);
                float w0 = __shfl_sync(0xffffffffu, S[ks][2], src_hi);
                float w1 = __shfl_sync(0xffffffffu, S[ks][3], src_hi);
                A[3] = __float_as_uint(odd ? w1 : w0);
            }
            #pragma unroll
            for (int j = 0; j < 8; j++) {
                unsigned b0 = Vs[(ks * 8 + l3) * VS_STRIDE + j * 8 + q];
                unsigned b1 = Vs[(ks * 8 + l3 + 4) * VS_STRIDE + j * 8 + q];
                mma_tf32(O[j], A, b0, b1);
            }
        }
    }

    const int bi = bh >> 4;
    const int h  = bh & 15;
    const float inv0 = 1.f / l_lo;
    const float inv1 = 1.f / l_hi;
    const int t0 = q0 + wrow + q;
    float* outp = g_A + (bi * Tn + t0) * Dn + h * DKn;
    #pragma unroll
    for (int j = 0; j < 8; j++) {
        *(float2*)&outp[j * 8 + 2 * l3] =
            make_float2(O[j][0] * inv0, O[j][1] * inv0);
        *(float2*)&outp[8 * Dn + j * 8 + 2 * l3] =
            make_float2(O[j][2] * inv1, O[j][3] * inv1);
    }
}

// ---------------------------------------------------------------------------
extern "C" void kernel_launch(void* const* d_in, const int* in_sizes, int n_in,
                              void* d_out, int out_size)
{
    const float* x    = (const float*)d_in[0];
    const float* wqkv = (const float*)d_in[1];
    const float* bqkv = (const float*)d_in[2];
    const float* wout = (const float*)d_in[3];
    const float* bout = (const float*)d_in[4];
    const float* fc   = (const float*)d_in[5];
    const float* fs   = (const float*)d_in[6];
    float* out = (float*)d_out;

    cudaFuncSetAttribute(qkv_mma_kernel,
                         cudaFuncAttributeMaxDynamicSharedMemorySize,
                         GEMM_SM_BYTES);
    cudaFuncSetAttribute(proj_mma_kernel,
                         cudaFuncAttributeMaxDynamicSharedMemorySize,
                         GEMM_SM_BYTES);

    qkv_mma_kernel<<<dim3(Nqkv/128, Mn/128), 256, GEMM_SM_BYTES>>>(x, wqkv, bqkv, fc, fs);
    attn_mma_kernel<<<dim3(Tn/128, Bn*Hn), 256>>>();
    proj_mma_kernel<<<dim3(Dn/128, Mn/128), 256, GEMM_SM_BYTES>>>(wout, bout, out);
}

// round 6
// speedup vs baseline: 1.8056x; 1.8056x over previous
#include <cuda_runtime.h>
#include <cuda_fp16.h>

#define Bn  2
#define Tn  2048
#define Dn  1024
#define Hn  16
#define DKn 64
#define Mn  (Bn*Tn)   // 4096
#define Nqkv (3*Dn)   // 3072

// Scratch (device globals — no allocations allowed). All fp16 now.
__device__ __half g_Q[Bn*Hn*Tn*DKn];   // [B,H,T,DK], pre-scaled by 1/8
__device__ __half g_K[Bn*Hn*Tn*DKn];
__device__ __half g_V[Bn*Hn*Tn*DKn];
__device__ __half g_A[Bn*Tn*Dn];       // attention output [B,T,D]

// ---------------------------------------------------------------------------
// helpers
// ---------------------------------------------------------------------------
__device__ __forceinline__ unsigned pack_h2(float lo, float hi) {
    __half2 h = __floats2half2_rn(lo, hi);   // .x = lo (even k), .y = hi
    return *reinterpret_cast<unsigned*>(&h);
}

__device__ __forceinline__ void ldsm4(unsigned& r0, unsigned& r1,
                                      unsigned& r2, unsigned& r3, unsigned addr) {
    asm volatile("ldmatrix.sync.aligned.m8n8.x4.shared.b16 {%0,%1,%2,%3}, [%4];"
                 : "=r"(r0), "=r"(r1), "=r"(r2), "=r"(r3) : "r"(addr));
}

__device__ __forceinline__ void ldsm4t(unsigned& r0, unsigned& r1,
                                       unsigned& r2, unsigned& r3, unsigned addr) {
    asm volatile("ldmatrix.sync.aligned.m8n8.x4.trans.shared.b16 {%0,%1,%2,%3}, [%4];"
                 : "=r"(r0), "=r"(r1), "=r"(r2), "=r"(r3) : "r"(addr));
}

__device__ __forceinline__ void mma_f16(float* c, const unsigned* a,
                                        unsigned b0, unsigned b1) {
    asm volatile(
        "mma.sync.aligned.m16n8k16.row.col.f32.f16.f16.f32 "
        "{%0,%1,%2,%3}, {%4,%5,%6,%7}, {%8,%9}, {%0,%1,%2,%3};\n"
        : "+f"(c[0]), "+f"(c[1]), "+f"(c[2]), "+f"(c[3])
        : "r"(a[0]), "r"(a[1]), "r"(a[2]), "r"(a[3]), "r"(b0), "r"(b1));
}

#define GS 72   // smem row stride in halves (144 B: ldmatrix conflict-free)

// ---------------------------------------------------------------------------
// fp16 GEMM mainloop: acc[128x128] += A[m0:+128,:] @ B[n0:+128,:]^T, k-tile 64.
// 8 warps (4m x 2n), warp tile 32x64. A operand fp32 (AHALF=0) or fp16 (=1).
// ---------------------------------------------------------------------------
template <int AHALF>
__device__ __forceinline__ void gemm_f16(
    const void* Ap_, const float* __restrict__ Wp,
    __half* smA, __half* smW, unsigned sA, unsigned sW,
    int m0, int n0, int tid, int lane, int wm, int wn, float acc[2][8][4])
{
    const int lrow = lane & 15;
    const int lcol = (lane >> 4) << 3;
    const int r0w  = wm * 32;
    const int nbw  = wn * 64;

    for (int kt = 0; kt < Dn / 64; kt++) {
        const int k0 = kt * 64;
        __syncthreads();
        if (AHALF) {
            const __half* Ap = (const __half*)Ap_;
            #pragma unroll
            for (int s = 0; s < 4; s++) {
                int idx = tid + 256 * s;
                int r = idx >> 3, c8 = (idx & 7) * 8;
                *(uint4*)&smA[r * GS + c8] =
                    *(const uint4*)&Ap[(m0 + r) * Dn + k0 + c8];
            }
        } else {
            const float* Ap = (const float*)Ap_;
            #pragma unroll
            for (int s = 0; s < 8; s++) {
                int idx = tid + 256 * s;
                int r = idx >> 4, c4 = (idx & 15) * 4;
                float4 v = *(const float4*)&Ap[(m0 + r) * Dn + k0 + c4];
                *(uint2*)&smA[r * GS + c4] =
                    make_uint2(pack_h2(v.x, v.y), pack_h2(v.z, v.w));
            }
        }
        #pragma unroll
        for (int s = 0; s < 8; s++) {
            int idx = tid + 256 * s;
            int r = idx >> 4, c4 = (idx & 15) * 4;
            float4 v = *(const float4*)&Wp[(n0 + r) * Dn + k0 + c4];
            *(uint2*)&smW[r * GS + c4] =
                make_uint2(pack_h2(v.x, v.y), pack_h2(v.z, v.w));
        }
        __syncthreads();

        #pragma unroll
        for (int ks = 0; ks < 4; ks++) {
            unsigned a[2][4];
            #pragma unroll
            for (int mt = 0; mt < 2; mt++)
                ldsm4(a[mt][0], a[mt][1], a[mt][2], a[mt][3],
                      sA + ((r0w + mt * 16 + lrow) * GS + ks * 16 + lcol) * 2);
            #pragma unroll
            for (int jj = 0; jj < 4; jj++) {
                unsigned b0, b1, b2, b3;
                ldsm4(b0, b1, b2, b3,
                      sW + ((nbw + jj * 16 + lrow) * GS + ks * 16 + lcol) * 2);
                #pragma unroll
                for (int mt = 0; mt < 2; mt++) {
                    mma_f16(acc[mt][2 * jj],     a[mt], b0, b2);
                    mma_f16(acc[mt][2 * jj + 1], a[mt], b1, b3);
                }
            }
        }
    }
}

// ---------------------------------------------------------------------------
// Kernel 1: QKV = x @ w_qkv^T + b_qkv, fused RoPE + 1/8 scale on q
// ---------------------------------------------------------------------------
__global__ __launch_bounds__(256, 2) void qkv_mma_kernel(
    const float* __restrict__ x, const float* __restrict__ w,
    const float* __restrict__ bias, const float* __restrict__ fc,
    const float* __restrict__ fs)
{
    __shared__ __half smA[128 * GS];
    __shared__ __half smW[128 * GS];
    const unsigned sA = (unsigned)__cvta_generic_to_shared(smA);
    const unsigned sW = (unsigned)__cvta_generic_to_shared(smW);
    const int tid  = threadIdx.x;
    const int warp = tid >> 5, lane = tid & 31;
    const int wm = warp & 3, wn = warp >> 2;
    const int m0 = blockIdx.y * 128;
    const int n0 = blockIdx.x * 128;

    float acc[2][8][4];
    #pragma unroll
    for (int mt = 0; mt < 2; mt++)
        #pragma unroll
        for (int j = 0; j < 8; j++)
            #pragma unroll
            for (int e = 0; e < 4; e++) acc[mt][j][e] = 0.f;

    gemm_f16<0>(x, w, smA, smW, sA, sW, m0, n0, tid, lane, wm, wn, acc);

    const int region = n0 >> 10;
    __half* dst = (region == 0) ? g_Q : (region == 1) ? g_K : g_V;
    const int rbase = m0 + wm * 32 + (lane >> 2);

    #pragma unroll
    for (int j = 0; j < 8; j++) {
        const int n  = n0 + wn * 64 + j * 8 + (lane & 3) * 2;
        const int h  = (n & 1023) >> 6;
        const int d  = n & 63;
        const int p  = d >> 1;
        const float bv0 = bias[n], bv1 = bias[n + 1];
        #pragma unroll
        for (int mt = 0; mt < 2; mt++) {
            #pragma unroll
            for (int half = 0; half < 2; half++) {
                const int r  = rbase + mt * 16 + half * 8;
                const int bi = r >> 11;
                const int t  = r & 2047;
                float re = acc[mt][j][half * 2 + 0] + bv0;
                float im = acc[mt][j][half * 2 + 1] + bv1;
                if (region < 2) {
                    float c = fc[t * (DKn / 2) + p];
                    float s = fs[t * (DKn / 2) + p];
                    float nre = re * c - im * s;
                    float nim = re * s + im * c;
                    re = nre; im = nim;
                    if (region == 0) { re *= 0.125f; im *= 0.125f; }
                }
                *(unsigned*)&dst[((bi * Hn + h) * Tn + t) * DKn + d] =
                    pack_h2(re, im);
            }
        }
    }
}

// ---------------------------------------------------------------------------
// Kernel 3: out = g_A @ w_out^T + b_out
// ---------------------------------------------------------------------------
__global__ __launch_bounds__(256, 2) void proj_mma_kernel(
    const float* __restrict__ w, const float* __restrict__ bias,
    float* __restrict__ out)
{
    __shared__ __half smA[128 * GS];
    __shared__ __half smW[128 * GS];
    const unsigned sA = (unsigned)__cvta_generic_to_shared(smA);
    const unsigned sW = (unsigned)__cvta_generic_to_shared(smW);
    const int tid  = threadIdx.x;
    const int warp = tid >> 5, lane = tid & 31;
    const int wm = warp & 3, wn = warp >> 2;
    const int m0 = blockIdx.y * 128;
    const int n0 = blockIdx.x * 128;

    float acc[2][8][4];
    #pragma unroll
    for (int mt = 0; mt < 2; mt++)
        #pragma unroll
        for (int j = 0; j < 8; j++)
            #pragma unroll
            for (int e = 0; e < 4; e++) acc[mt][j][e] = 0.f;

    gemm_f16<1>(g_A, w, smA, smW, sA, sW, m0, n0, tid, lane, wm, wn, acc);

    const int rbase = m0 + wm * 32 + (lane >> 2);
    #pragma unroll
    for (int j = 0; j < 8; j++) {
        const int n = n0 + wn * 64 + j * 8 + (lane & 3) * 2;
        const float bv0 = bias[n], bv1 = bias[n + 1];
        #pragma unroll
        for (int mt = 0; mt < 2; mt++) {
            #pragma unroll
            for (int half = 0; half < 2; half++) {
                const int r = rbase + mt * 16 + half * 8;
                *(float2*)&out[r * Dn + n] =
                    make_float2(acc[mt][j][half * 2 + 0] + bv0,
                                acc[mt][j][half * 2 + 1] + bv1);
            }
        }
    }
}

// ---------------------------------------------------------------------------
// Kernel 2: causal flash attention, fp16 mma (m16n8k16).
// BQ=128 (8 warps x 16 q-rows), BK=64. Warp-local online softmax.
// P A-fragments come directly from S accumulators (no shuffles, no smem).
// ---------------------------------------------------------------------------
__global__ __launch_bounds__(256, 2) void attn_mma_kernel()
{
    __shared__ __half smKV[128 * GS];          // 18432 B
    __half* Ks = smKV;                          // [64 tok][GS]
    __half* Vs = smKV + 64 * GS;                // [64 tok][GS]
    __half* Qs = smKV;                          // Q staging alias [128 q][GS]
    const unsigned sK = (unsigned)__cvta_generic_to_shared(Ks);
    const unsigned sV = (unsigned)__cvta_generic_to_shared(Vs);
    const unsigned sQ = sK;

    const int tid  = threadIdx.x;
    const int warp = tid >> 5, lane = tid & 31;
    const int q    = lane >> 2, l3 = lane & 3;
    const int lrow = lane & 15;
    const int lcol = (lane >> 4) << 3;
    const int qblk = (int)gridDim.x - 1 - (int)blockIdx.x;
    const int bh   = blockIdx.y;
    const int q0   = qblk * 128;

    const __half* Qg = g_Q + (bh * Tn + q0) * DKn;
    const __half* Kg = g_K + bh * Tn * DKn;
    const __half* Vg = g_V + bh * Tn * DKn;

    // Stage Q, pull A-fragments into registers
    #pragma unroll
    for (int s = 0; s < 4; s++) {
        int idx = tid + 256 * s;
        int r = idx >> 3, c8 = (idx & 7) * 8;
        *(uint4*)&Qs[r * GS + c8] = *(const uint4*)&Qg[r * DKn + c8];
    }
    __syncthreads();

    const int wrow = warp * 16;
    unsigned Qf[4][4];
    #pragma unroll
    for (int ks = 0; ks < 4; ks++)
        ldsm4(Qf[ks][0], Qf[ks][1], Qf[ks][2], Qf[ks][3],
              sQ + ((wrow + lrow) * GS + ks * 16 + lcol) * 2);

    float O[8][4];
    #pragma unroll
    for (int j = 0; j < 8; j++)
        #pragma unroll
        for (int e = 0; e < 4; e++) O[j][e] = 0.f;
    float m_lo = -1e30f, m_hi = -1e30f, l_lo = 0.f, l_hi = 0.f;

    const int wr_lo = q0 + wrow;
    const int wr_hi = wr_lo + 15;
    const int n_kt  = 2 * qblk + 2;

    for (int kt = 0; kt < n_kt; kt++) {
        const int k0 = kt * 64;
        __syncthreads();   // prior tile reads (incl. Q ldmatrix) complete
        #pragma unroll
        for (int s = 0; s < 2; s++) {
            int idx = tid + 256 * s;
            int r = idx >> 3, c8 = (idx & 7) * 8;
            *(uint4*)&Ks[r * GS + c8] = *(const uint4*)&Kg[(k0 + r) * DKn + c8];
            *(uint4*)&Vs[r * GS + c8] = *(const uint4*)&Vg[(k0 + r) * DKn + c8];
        }
        __syncthreads();

        if (k0 > wr_hi) continue;   // fully masked for this warp

        // S = Q K^T  (Q pre-scaled by 1/8)
        float S[8][4];
        #pragma unroll
        for (int j = 0; j < 8; j++)
            #pragma unroll
            for (int e = 0; e < 4; e++) S[j][e] = 0.f;

        #pragma unroll
        for (int ks = 0; ks < 4; ks++) {
            #pragma unroll
            for (int jj = 0; jj < 4; jj++) {
                unsigned b0, b1, b2, b3;
                ldsm4(b0, b1, b2, b3,
                      sK + ((jj * 16 + lrow) * GS + ks * 16 + lcol) * 2);
                mma_f16(S[2 * jj],     Qf[ks], b0, b2);
                mma_f16(S[2 * jj + 1], Qf[ks], b1, b3);
            }
        }

        // causal mask
        if (k0 + 63 > wr_lo) {
            const int r0 = wr_lo + q;
            #pragma unroll
            for (int j = 0; j < 8; j++) {
                const int c = k0 + j * 8 + 2 * l3;
                if (c     > r0)     S[j][0] = -1e30f;
                if (c + 1 > r0)     S[j][1] = -1e30f;
                if (c     > r0 + 8) S[j][2] = -1e30f;
                if (c + 1 > r0 + 8) S[j][3] = -1e30f;
            }
        }

        // online softmax (rows warp-local; reduce over quad lanes)
        float mx0 = -1e30f, mx1 = -1e30f;
        #pragma unroll
        for (int j = 0; j < 8; j++) {
            mx0 = fmaxf(mx0, fmaxf(S[j][0], S[j][1]));
            mx1 = fmaxf(mx1, fmaxf(S[j][2], S[j][3]));
        }
        mx0 = fmaxf(mx0, __shfl_xor_sync(0xffffffffu, mx0, 1));
        mx0 = fmaxf(mx0, __shfl_xor_sync(0xffffffffu, mx0, 2));
        mx1 = fmaxf(mx1, __shfl_xor_sync(0xffffffffu, mx1, 1));
        mx1 = fmaxf(mx1, __shfl_xor_sync(0xffffffffu, mx1, 2));

        const float mn0 = fmaxf(m_lo, mx0);
        const float mn1 = fmaxf(m_hi, mx1);
        const float a0  = __expf(m_lo - mn0);
        const float a1  = __expf(m_hi - mn1);
        m_lo = mn0; m_hi = mn1;

        float s0 = 0.f, s1 = 0.f;
        #pragma unroll
        for (int j = 0; j < 8; j++) {
            S[j][0] = __expf(S[j][0] - mn0);
            S[j][1] = __expf(S[j][1] - mn0);
            s0 += S[j][0] + S[j][1];
            S[j][2] = __expf(S[j][2] - mn1);
            S[j][3] = __expf(S[j][3] - mn1);
            s1 += S[j][2] + S[j][3];
        }
        s0 += __shfl_xor_sync(0xffffffffu, s0, 1);
        s0 += __shfl_xor_sync(0xffffffffu, s0, 2);
        s1 += __shfl_xor_sync(0xffffffffu, s1, 1);
        s1 += __shfl_xor_sync(0xffffffffu, s1, 2);
        l_lo = l_lo * a0 + s0;
        l_hi = l_hi * a1 + s1;

        #pragma unroll
        for (int j = 0; j < 8; j++) {
            O[j][0] *= a0; O[j][1] *= a0;
            O[j][2] *= a1; O[j][3] *= a1;
        }

        // O += P @ V : P A-frags are packed S accumulators (no shuffle!)
        #pragma unroll
        for (int ksp = 0; ksp < 4; ksp++) {
            unsigned A[4];
            A[0] = pack_h2(S[2 * ksp][0],     S[2 * ksp][1]);
            A[1] = pack_h2(S[2 * ksp][2],     S[2 * ksp][3]);
            A[2] = pack_h2(S[2 * ksp + 1][0], S[2 * ksp + 1][1]);
            A[3] = pack_h2(S[2 * ksp + 1][2], S[2 * ksp + 1][3]);
            #pragma unroll
            for (int dd = 0; dd < 4; dd++) {
                unsigned b0, b1, b2, b3;
                ldsm4t(b0, b1, b2, b3,
                       sV + ((ksp * 16 + lrow) * GS + dd * 16 + lcol) * 2);
                mma_f16(O[2 * dd],     A, b0, b1);
                mma_f16(O[2 * dd + 1], A, b2, b3);
            }
        }
    }

    // normalize + write to g_A [B,T,D] (fp16)
    const int bi = bh >> 4;
    const int h  = bh & 15;
    const float inv0 = 1.f / l_lo;
    const float inv1 = 1.f / l_hi;
    const int t0 = q0 + wrow + q;
    __half* outp = g_A + (bi * Tn + t0) * Dn + h * DKn;
    #pragma unroll
    for (int j = 0; j < 8; j++) {
        *(unsigned*)&outp[j * 8 + 2 * l3] =
            pack_h2(O[j][0] * inv0, O[j][1] * inv0);
        *(unsigned*)&outp[8 * Dn + j * 8 + 2 * l3] =
            pack_h2(O[j][2] * inv1, O[j][3] * inv1);
    }
}

// ---------------------------------------------------------------------------
extern "C" void kernel_launch(void* const* d_in, const int* in_sizes, int n_in,
                              void* d_out, int out_size)
{
    const float* x    = (const float*)d_in[0];
    const float* wqkv = (const float*)d_in[1];
    const float* bqkv = (const float*)d_in[2];
    const float* wout = (const float*)d_in[3];
    const float* bout = (const float*)d_in[4];
    const float* fc   = (const float*)d_in[5];
    const float* fs   = (const float*)d_in[6];
    float* out = (float*)d_out;

    qkv_mma_kernel<<<dim3(Nqkv/128, Mn/128), 256>>>(x, wqkv, bqkv, fc, fs);
    attn_mma_kernel<<<dim3(Tn/128, Bn*Hn), 256>>>();
    proj_mma_kernel<<<dim3(Dn/128, Mn/128), 256>>>(wout, bout, out);
}

// round 8
// speedup vs baseline: 1.9479x; 1.0788x over previous
#include <cuda_runtime.h>
#include <cuda_fp16.h>
#include <cstdint>

#define Bn  2
#define Tn  2048
#define Dn  1024
#define Hn  16
#define DKn 64
#define Mn  (Bn*Tn)   // 4096
#define Nqkv (3*Dn)   // 3072

// Scratch (device globals — no allocations allowed)
__device__ __half g_Q[Bn*Hn*Tn*DKn];
__device__ __half g_K[Bn*Hn*Tn*DKn];
__device__ __half g_V[Bn*Hn*Tn*DKn];
__device__ __half g_A[Bn*Tn*Dn];
__device__ __half g_x16[Mn*Dn];
__device__ __half g_wq16[Nqkv*Dn];
__device__ __half g_wo16[Dn*Dn];

// ---------------------------------------------------------------------------
// helpers
// ---------------------------------------------------------------------------
__device__ __forceinline__ unsigned pack_h2(float lo, float hi) {
    __half2 h = __floats2half2_rn(lo, hi);
    return *reinterpret_cast<unsigned*>(&h);
}
__device__ __forceinline__ void ldsm4(unsigned& r0, unsigned& r1,
                                      unsigned& r2, unsigned& r3, unsigned addr) {
    asm volatile("ldmatrix.sync.aligned.m8n8.x4.shared.b16 {%0,%1,%2,%3}, [%4];"
                 : "=r"(r0), "=r"(r1), "=r"(r2), "=r"(r3) : "r"(addr));
}
__device__ __forceinline__ void ldsm4t(unsigned& r0, unsigned& r1,
                                       unsigned& r2, unsigned& r3, unsigned addr) {
    asm volatile("ldmatrix.sync.aligned.m8n8.x4.trans.shared.b16 {%0,%1,%2,%3}, [%4];"
                 : "=r"(r0), "=r"(r1), "=r"(r2), "=r"(r3) : "r"(addr));
}
__device__ __forceinline__ void mma_f16(float* c, const unsigned* a,
                                        unsigned b0, unsigned b1) {
    asm volatile(
        "mma.sync.aligned.m16n8k16.row.col.f32.f16.f16.f32 "
        "{%0,%1,%2,%3}, {%4,%5,%6,%7}, {%8,%9}, {%0,%1,%2,%3};\n"
        : "+f"(c[0]), "+f"(c[1]), "+f"(c[2]), "+f"(c[3])
        : "r"(a[0]), "r"(a[1]), "r"(a[2]), "r"(a[3]), "r"(b0), "r"(b1));
}
__device__ __forceinline__ void cpa16(uint32_t dst, const void* src) {
    asm volatile("cp.async.cg.shared.global [%0], [%1], 16;"
                 :: "r"(dst), "l"(src) : "memory");
}
#define CP_COMMIT() asm volatile("cp.async.commit_group;" ::: "memory")
#define CP_WAIT(n)  asm volatile("cp.async.wait_group %0;" :: "n"(n) : "memory")

#define GS 72                         // smem row stride (halves); 144 B rows
#define STG_BYTES (128 * GS * 2)      // one GEMM operand stage: 18432 B
#define GEMM_SM_BYTES (4 * STG_BYTES) // 2 stages x (A + W) = 73728 B

// ---------------------------------------------------------------------------
// fp32 -> fp16 convert, n multiple of 2048
// ---------------------------------------------------------------------------
__global__ __launch_bounds__(256) void f2h_kernel(
    const float* __restrict__ s, __half* __restrict__ d)
{
    int i = (blockIdx.x * 256 + threadIdx.x) * 8;
    float4 a = *(const float4*)(s + i);
    float4 b = *(const float4*)(s + i + 4);
    uint4 o;
    o.x = pack_h2(a.x, a.y); o.y = pack_h2(a.z, a.w);
    o.z = pack_h2(b.x, b.y); o.w = pack_h2(b.z, b.w);
    *(uint4*)(d + i) = o;
}

// ---------------------------------------------------------------------------
// fp16 GEMM mainloop, cp.async 2-stage pipeline (prefetch distance 2):
//   acc[128x128] += A[m0:+128,:] @ B[n0:+128,:]^T, K = Dn, k-tile 64.
// Stage s (bytes): A at s*2*STG_BYTES, W at s*2*STG_BYTES + STG_BYTES.
// ---------------------------------------------------------------------------
__device__ __forceinline__ void gemm_fill(
    const __half* __restrict__ Ag, const __half* __restrict__ Bg,
    uint32_t smBase, int kt, int stage, int tid)
{
    const __half* a = Ag + kt * 64;
    const __half* b = Bg + kt * 64;
    const uint32_t sA = smBase + stage * 2 * STG_BYTES;
    const uint32_t sW = sA + STG_BYTES;
    #pragma unroll
    for (int s = 0; s < 4; s++) {
        int i = tid + 256 * s;
        int r = i >> 3, c8 = (i & 7) * 8;
        uint32_t off = (uint32_t)(r * GS + c8) * 2;
        cpa16(sA + off, a + r * Dn + c8);
        cpa16(sW + off, b + r * Dn + c8);
    }
    CP_COMMIT();
}

__device__ __forceinline__ void gemm_pipe(
    const __half* __restrict__ Ag, const __half* __restrict__ Bg,
    uint32_t smBase, int lane, int wm, int wn, int tid, float acc[2][8][4])
{
    const int lrow = lane & 15;
    const int lcol = (lane >> 4) << 3;
    const int r0w  = wm * 32;
    const int nbw  = wn * 64;

    gemm_fill(Ag, Bg, smBase, 0, 0, tid);
    gemm_fill(Ag, Bg, smBase, 1, 1, tid);

    for (int kt = 0; kt < Dn / 64; kt++) {
        if (kt + 1 < Dn / 64) CP_WAIT(1); else CP_WAIT(0);
        __syncthreads();

        const uint32_t sA = smBase + (kt & 1) * 2 * STG_BYTES;
        const uint32_t sW = sA + STG_BYTES;
        #pragma unroll
        for (int ks = 0; ks < 4; ks++) {
            unsigned a[2][4];
            #pragma unroll
            for (int mt = 0; mt < 2; mt++)
                ldsm4(a[mt][0], a[mt][1], a[mt][2], a[mt][3],
                      sA + ((r0w + mt * 16 + lrow) * GS + ks * 16 + lcol) * 2);
            #pragma unroll
            for (int jj = 0; jj < 4; jj++) {
                unsigned b0, b1, b2, b3;
                ldsm4(b0, b1, b2, b3,
                      sW + ((nbw + jj * 16 + lrow) * GS + ks * 16 + lcol) * 2);
                #pragma unroll
                for (int mt = 0; mt < 2; mt++) {
                    mma_f16(acc[mt][2 * jj],     a[mt], b0, b2);
                    mma_f16(acc[mt][2 * jj + 1], a[mt], b1, b3);
                }
            }
        }
        __syncthreads();
        if (kt + 2 < Dn / 64)
            gemm_fill(Ag, Bg, smBase, kt + 2, kt & 1, tid);
    }
}

// ---------------------------------------------------------------------------
// Kernel 1: QKV = x @ w_qkv^T + b_qkv, fused RoPE + 1/8 scale on q
// ---------------------------------------------------------------------------
__global__ __launch_bounds__(256, 2) void qkv_mma_kernel(
    const float* __restrict__ bias, const float* __restrict__ fc,
    const float* __restrict__ fs)
{
    extern __shared__ __half dynsm[];
    const uint32_t smBase = (uint32_t)__cvta_generic_to_shared(dynsm);
    const int tid  = threadIdx.x;
    const int warp = tid >> 5, lane = tid & 31;
    const int wm = warp & 3, wn = warp >> 2;
    const int m0 = blockIdx.y * 128;
    const int n0 = blockIdx.x * 128;

    float acc[2][8][4];
    #pragma unroll
    for (int mt = 0; mt < 2; mt++)
        #pragma unroll
        for (int j = 0; j < 8; j++)
            #pragma unroll
            for (int e = 0; e < 4; e++) acc[mt][j][e] = 0.f;

    gemm_pipe(g_x16 + m0 * Dn, g_wq16 + n0 * Dn, smBase, lane, wm, wn, tid, acc);

    const int region = n0 >> 10;
    __half* dst = (region == 0) ? g_Q : (region == 1) ? g_K : g_V;
    const int rbase = m0 + wm * 32 + (lane >> 2);

    #pragma unroll
    for (int j = 0; j < 8; j++) {
        const int n  = n0 + wn * 64 + j * 8 + (lane & 3) * 2;
        const int h  = (n & 1023) >> 6;
        const int d  = n & 63;
        const int p  = d >> 1;
        const float bv0 = bias[n], bv1 = bias[n + 1];
        #pragma unroll
        for (int mt = 0; mt < 2; mt++) {
            #pragma unroll
            for (int half = 0; half < 2; half++) {
                const int r  = rbase + mt * 16 + half * 8;
                const int bi = r >> 11;
                const int t  = r & 2047;
                float re = acc[mt][j][half * 2 + 0] + bv0;
                float im = acc[mt][j][half * 2 + 1] + bv1;
                if (region < 2) {
                    float c = fc[t * (DKn / 2) + p];
                    float s = fs[t * (DKn / 2) + p];
                    float nre = re * c - im * s;
                    float nim = re * s + im * c;
                    re = nre; im = nim;
                    if (region == 0) { re *= 0.125f; im *= 0.125f; }
                }
                *(unsigned*)&dst[((bi * Hn + h) * Tn + t) * DKn + d] =
                    pack_h2(re, im);
            }
        }
    }
}

// ---------------------------------------------------------------------------
// Kernel 3: out = g_A @ w_out^T + b_out (fp32 output)
// ---------------------------------------------------------------------------
__global__ __launch_bounds__(256, 2) void proj_mma_kernel(
    const float* __restrict__ bias, float* __restrict__ out)
{
    extern __shared__ __half dynsm[];
    const uint32_t smBase = (uint32_t)__cvta_generic_to_shared(dynsm);
    const int tid  = threadIdx.x;
    const int warp = tid >> 5, lane = tid & 31;
    const int wm = warp & 3, wn = warp >> 2;
    const int m0 = blockIdx.y * 128;
    const int n0 = blockIdx.x * 128;

    float acc[2][8][4];
    #pragma unroll
    for (int mt = 0; mt < 2; mt++)
        #pragma unroll
        for (int j = 0; j < 8; j++)
            #pragma unroll
            for (int e = 0; e < 4; e++) acc[mt][j][e] = 0.f;

    gemm_pipe(g_A + m0 * Dn, g_wo16 + n0 * Dn, smBase, lane, wm, wn, tid, acc);

    const int rbase = m0 + wm * 32 + (lane >> 2);
    #pragma unroll
    for (int j = 0; j < 8; j++) {
        const int n = n0 + wn * 64 + j * 8 + (lane & 3) * 2;
        const float bv0 = bias[n], bv1 = bias[n + 1];
        #pragma unroll
        for (int mt = 0; mt < 2; mt++) {
            #pragma unroll
            for (int half = 0; half < 2; half++) {
                const int r = rbase + mt * 16 + half * 8;
                *(float2*)&out[r * Dn + n] =
                    make_float2(acc[mt][j][half * 2 + 0] + bv0,
                                acc[mt][j][half * 2 + 1] + bv1);
            }
        }
    }
}

// ---------------------------------------------------------------------------
// Kernel 2: causal flash attention, fp16 mma, cp.async 2-stage KV pipeline.
// BQ=128 (8 warps x 16 q-rows), BK=64. Warp-local online softmax.
// smem stage s: K at s*2*KSTG, V at +KSTG (KSTG = 64*GS*2 bytes).
// ---------------------------------------------------------------------------
#define KSTG_BYTES (64 * GS * 2)                  // 9216 B
#define ATT_SM_HALVES (4 * 64 * GS)               // 18432 halves = 36864 B

__device__ __forceinline__ void attn_fill(
    const __half* __restrict__ Kg, const __half* __restrict__ Vg,
    uint32_t smBase, int kt, int stage, int tid)
{
    const int k0 = kt * 64;
    const uint32_t sK = smBase + stage * 2 * KSTG_BYTES;
    const uint32_t sV = sK + KSTG_BYTES;
    #pragma unroll
    for (int s = 0; s < 2; s++) {
        int i = tid + 256 * s;
        int r = i >> 3, c8 = (i & 7) * 8;
        uint32_t off = (uint32_t)(r * GS + c8) * 2;
        cpa16(sK + off, Kg + (k0 + r) * DKn + c8);
        cpa16(sV + off, Vg + (k0 + r) * DKn + c8);
    }
    CP_COMMIT();
}

__global__ __launch_bounds__(256, 2) void attn_mma_kernel()
{
    __shared__ __half smKV[ATT_SM_HALVES];
    const uint32_t smBase = (uint32_t)__cvta_generic_to_shared(smKV);

    const int tid  = threadIdx.x;
    const int warp = tid >> 5, lane = tid & 31;
    const int q    = lane >> 2, l3 = lane & 3;
    const int lrow = lane & 15;
    const int lcol = (lane >> 4) << 3;
    const int qblk = (int)gridDim.x - 1 - (int)blockIdx.x;
    const int bh   = blockIdx.y;
    const int q0   = qblk * 128;

    const __half* Qg = g_Q + (bh * Tn + q0) * DKn;
    const __half* Kg = g_K + bh * Tn * DKn;
    const __half* Vg = g_V + bh * Tn * DKn;

    // Stage Q into smem (aliases KV stages), pull fragments, then release.
    #pragma unroll
    for (int s = 0; s < 4; s++) {
        int idx = tid + 256 * s;
        int r = idx >> 3, c8 = (idx & 7) * 8;
        *(uint4*)&smKV[r * GS + c8] = *(const uint4*)&Qg[r * DKn + c8];
    }
    __syncthreads();

    const int wrow = warp * 16;
    unsigned Qf[4][4];
    #pragma unroll
    for (int ks = 0; ks < 4; ks++)
        ldsm4(Qf[ks][0], Qf[ks][1], Qf[ks][2], Qf[ks][3],
              smBase + ((wrow + lrow) * GS + ks * 16 + lcol) * 2);
    __syncthreads();   // all warps done reading Q before KV overwrites

    float O[8][4];
    #pragma unroll
    for (int j = 0; j < 8; j++)
        #pragma unroll
        for (int e = 0; e < 4; e++) O[j][e] = 0.f;
    float m_lo = -1e30f, m_hi = -1e30f, l_lo = 0.f, l_hi = 0.f;

    const int wr_lo = q0 + wrow;
    const int wr_hi = wr_lo + 15;
    const int n_kt  = 2 * qblk + 2;

    attn_fill(Kg, Vg, smBase, 0, 0, tid);
    attn_fill(Kg, Vg, smBase, 1, 1, tid);

    for (int kt = 0; kt < n_kt; kt++) {
        if (kt + 1 < n_kt) CP_WAIT(1); else CP_WAIT(0);
        __syncthreads();

        const int k0 = kt * 64;
        if (k0 <= wr_hi) {
            const uint32_t sK = smBase + (kt & 1) * 2 * KSTG_BYTES;
            const uint32_t sV = sK + KSTG_BYTES;

            float S[8][4];
            #pragma unroll
            for (int j = 0; j < 8; j++)
                #pragma unroll
                for (int e = 0; e < 4; e++) S[j][e] = 0.f;

            #pragma unroll
            for (int ks = 0; ks < 4; ks++) {
                #pragma unroll
                for (int jj = 0; jj < 4; jj++) {
                    unsigned b0, b1, b2, b3;
                    ldsm4(b0, b1, b2, b3,
                          sK + ((jj * 16 + lrow) * GS + ks * 16 + lcol) * 2);
                    mma_f16(S[2 * jj],     Qf[ks], b0, b2);
                    mma_f16(S[2 * jj + 1], Qf[ks], b1, b3);
                }
            }

            if (k0 + 63 > wr_lo) {
                const int r0 = wr_lo + q;
                #pragma unroll
                for (int j = 0; j < 8; j++) {
                    const int c = k0 + j * 8 + 2 * l3;
                    if (c     > r0)     S[j][0] = -1e30f;
                    if (c + 1 > r0)     S[j][1] = -1e30f;
                    if (c     > r0 + 8) S[j][2] = -1e30f;
                    if (c + 1 > r0 + 8) S[j][3] = -1e30f;
                }
            }

            float mx0 = -1e30f, mx1 = -1e30f;
            #pragma unroll
            for (int j = 0; j < 8; j++) {
                mx0 = fmaxf(mx0, fmaxf(S[j][0], S[j][1]));
                mx1 = fmaxf(mx1, fmaxf(S[j][2], S[j][3]));
            }
            mx0 = fmaxf(mx0, __shfl_xor_sync(0xffffffffu, mx0, 1));
            mx0 = fmaxf(mx0, __shfl_xor_sync(0xffffffffu, mx0, 2));
            mx1 = fmaxf(mx1, __shfl_xor_sync(0xffffffffu, mx1, 1));
            mx1 = fmaxf(mx1, __shfl_xor_sync(0xffffffffu, mx1, 2));

            const float mn0 = fmaxf(m_lo, mx0);
            const float mn1 = fmaxf(m_hi, mx1);
            const float a0  = __expf(m_lo - mn0);
            const float a1  = __expf(m_hi - mn1);
            m_lo = mn0; m_hi = mn1;

            float s0 = 0.f, s1 = 0.f;
            #pragma unroll
            for (int j = 0; j < 8; j++) {
                S[j][0] = __expf(S[j][0] - mn0);
                S[j][1] = __expf(S[j][1] - mn0);
                s0 += S[j][0] + S[j][1];
                S[j][2] = __expf(S[j][2] - mn1);
                S[j][3] = __expf(S[j][3] - mn1);
                s1 += S[j][2] + S[j][3];
            }
            s0 += __shfl_xor_sync(0xffffffffu, s0, 1);
            s0 += __shfl_xor_sync(0xffffffffu, s0, 2);
            s1 += __shfl_xor_sync(0xffffffffu, s1, 1);
            s1 += __shfl_xor_sync(0xffffffffu, s1, 2);
            l_lo = l_lo * a0 + s0;
            l_hi = l_hi * a1 + s1;

            #pragma unroll
            for (int j = 0; j < 8; j++) {
                O[j][0] *= a0; O[j][1] *= a0;
                O[j][2] *= a1; O[j][3] *= a1;
            }

            #pragma unroll
            for (int ksp = 0; ksp < 4; ksp++) {
                unsigned A[4];
                A[0] = pack_h2(S[2 * ksp][0],     S[2 * ksp][1]);
                A[1] = pack_h2(S[2 * ksp][2],     S[2 * ksp][3]);
                A[2] = pack_h2(S[2 * ksp + 1][0], S[2 * ksp + 1][1]);
                A[3] = pack_h2(S[2 * ksp + 1][2], S[2 * ksp + 1][3]);
                #pragma unroll
                for (int dd = 0; dd < 4; dd++) {
                    unsigned b0, b1, b2, b3;
                    ldsm4t(b0, b1, b2, b3,
                           sV + ((ksp * 16 + lrow) * GS + dd * 16 + lcol) * 2);
                    mma_f16(O[2 * dd],     A, b0, b1);
                    mma_f16(O[2 * dd + 1], A, b2, b3);
                }
            }
        }
        __syncthreads();
        if (kt + 2 < n_kt)
            attn_fill(Kg, Vg, smBase, kt + 2, kt & 1, tid);
    }

    const int bi = bh >> 4;
    const int h  = bh & 15;
    const float inv0 = 1.f / l_lo;
    const float inv1 = 1.f / l_hi;
    const int t0 = q0 + wrow + q;
    __half* outp = g_A + (bi * Tn + t0) * Dn + h * DKn;
    #pragma unroll
    for (int j = 0; j < 8; j++) {
        *(unsigned*)&outp[j * 8 + 2 * l3] =
            pack_h2(O[j][0] * inv0, O[j][1] * inv0);
        *(unsigned*)&outp[8 * Dn + j * 8 + 2 * l3] =
            pack_h2(O[j][2] * inv1, O[j][3] * inv1);
    }
}

// ---------------------------------------------------------------------------
extern "C" void kernel_launch(void* const* d_in, const int* in_sizes, int n_in,
                              void* d_out, int out_size)
{
    const float* x    = (const float*)d_in[0];
    const float* wqkv = (const float*)d_in[1];
    const float* bqkv = (const float*)d_in[2];
    const float* wout = (const float*)d_in[3];
    const float* bout = (const float*)d_in[4];
    const float* fc   = (const float*)d_in[5];
    const float* fs   = (const float*)d_in[6];
    float* out = (float*)d_out;

    __half* dx;  cudaGetSymbolAddress((void**)&dx,  g_x16);
    __half* dwq; cudaGetSymbolAddress((void**)&dwq, g_wq16);
    __half* dwo; cudaGetSymbolAddress((void**)&dwo, g_wo16);

    cudaFuncSetAttribute(qkv_mma_kernel,
                         cudaFuncAttributeMaxDynamicSharedMemorySize,
                         GEMM_SM_BYTES);
    cudaFuncSetAttribute(proj_mma_kernel,
                         cudaFuncAttributeMaxDynamicSharedMemorySize,
                         GEMM_SM_BYTES);

    f2h_kernel<<<Mn * Dn / 2048, 256>>>(x, dx);
    f2h_kernel<<<Nqkv * Dn / 2048, 256>>>(wqkv, dwq);
    f2h_kernel<<<Dn * Dn / 2048, 256>>>(wout, dwo);

    qkv_mma_kernel<<<dim3(Nqkv / 128, Mn / 128), 256, GEMM_SM_BYTES>>>(bqkv, fc, fs);
    attn_mma_kernel<<<dim3(Tn / 128, Bn * Hn), 256>>>();
    proj_mma_kernel<<<dim3(Dn / 128, Mn / 128), 256, GEMM_SM_BYTES>>>(bout, out);
}

// round 9
// speedup vs baseline: 1.9607x; 1.0066x over previous
#include <cuda_runtime.h>
#include <cuda_fp16.h>
#include <cstdint>

#define Bn  2
#define Tn  2048
#define Dn  1024
#define Hn  16
#define DKn 64
#define Mn  (Bn*Tn)   // 4096
#define Nqkv (3*Dn)   // 3072
#define QSCALE 0.1803368801111204f   // (1/8) * log2(e)

// Scratch (device globals — no allocations allowed)
__device__ __half g_Q[Bn*Hn*Tn*DKn];
__device__ __half g_K[Bn*Hn*Tn*DKn];
__device__ __half g_V[Bn*Hn*Tn*DKn];
__device__ __half g_A[Bn*Tn*Dn];
__device__ __half g_x16[Mn*Dn];
__device__ __half g_wq16[Nqkv*Dn];
__device__ __half g_wo16[Dn*Dn];

// ---------------------------------------------------------------------------
// helpers
// ---------------------------------------------------------------------------
__device__ __forceinline__ unsigned pack_h2(float lo, float hi) {
    __half2 h = __floats2half2_rn(lo, hi);
    return *reinterpret_cast<unsigned*>(&h);
}
__device__ __forceinline__ float fex2(float x) {
    float r;
    asm("ex2.approx.f32 %0, %1;" : "=f"(r) : "f"(x));
    return r;
}
__device__ __forceinline__ void ldsm4(unsigned& r0, unsigned& r1,
                                      unsigned& r2, unsigned& r3, unsigned addr) {
    asm volatile("ldmatrix.sync.aligned.m8n8.x4.shared.b16 {%0,%1,%2,%3}, [%4];"
                 : "=r"(r0), "=r"(r1), "=r"(r2), "=r"(r3) : "r"(addr));
}
__device__ __forceinline__ void ldsm4t(unsigned& r0, unsigned& r1,
                                       unsigned& r2, unsigned& r3, unsigned addr) {
    asm volatile("ldmatrix.sync.aligned.m8n8.x4.trans.shared.b16 {%0,%1,%2,%3}, [%4];"
                 : "=r"(r0), "=r"(r1), "=r"(r2), "=r"(r3) : "r"(addr));
}
__device__ __forceinline__ void mma_f16(float* c, const unsigned* a,
                                        unsigned b0, unsigned b1) {
    asm volatile(
        "mma.sync.aligned.m16n8k16.row.col.f32.f16.f16.f32 "
        "{%0,%1,%2,%3}, {%4,%5,%6,%7}, {%8,%9}, {%0,%1,%2,%3};\n"
        : "+f"(c[0]), "+f"(c[1]), "+f"(c[2]), "+f"(c[3])
        : "r"(a[0]), "r"(a[1]), "r"(a[2]), "r"(a[3]), "r"(b0), "r"(b1));
}
__device__ __forceinline__ void cpa16(uint32_t dst, const void* src) {
    asm volatile("cp.async.cg.shared.global [%0], [%1], 16;"
                 :: "r"(dst), "l"(src) : "memory");
}
#define CP_COMMIT() asm volatile("cp.async.commit_group;" ::: "memory")
#define CP_WAIT(n)  asm volatile("cp.async.wait_group %0;" :: "n"(n) : "memory")

#define GS 72                          // smem row stride (halves); 144 B rows
#define STG_BYTES (128 * GS * 2)       // one GEMM operand stage: 18432 B
#define GEMM_STAGE_STRIDE (2 * STG_BYTES)
#define GEMM_SM_BYTES (3 * GEMM_STAGE_STRIDE)   // 110592 B

// ---------------------------------------------------------------------------
// fp32 -> fp16 convert, n multiple of 2048
// ---------------------------------------------------------------------------
__global__ __launch_bounds__(256) void f2h_kernel(
    const float* __restrict__ s, __half* __restrict__ d)
{
    int i = (blockIdx.x * 256 + threadIdx.x) * 8;
    float4 a = *(const float4*)(s + i);
    float4 b = *(const float4*)(s + i + 4);
    uint4 o;
    o.x = pack_h2(a.x, a.y); o.y = pack_h2(a.z, a.w);
    o.z = pack_h2(b.x, b.y); o.w = pack_h2(b.z, b.w);
    *(uint4*)(d + i) = o;
}

// ---------------------------------------------------------------------------
// fp16 GEMM mainloop, 3-stage cp.async ring, ONE barrier per k-tile.
//   acc[128x128] += A[m0:+128,:] @ B[n0:+128,:]^T, K = Dn, k-tile 64.
// ---------------------------------------------------------------------------
__device__ __forceinline__ void gemm_fill(
    const __half* __restrict__ Ag, const __half* __restrict__ Bg,
    uint32_t smBase, int kt, int stage, int tid)
{
    const __half* a = Ag + kt * 64;
    const __half* b = Bg + kt * 64;
    const uint32_t sA = smBase + stage * GEMM_STAGE_STRIDE;
    const uint32_t sW = sA + STG_BYTES;
    #pragma unroll
    for (int s = 0; s < 4; s++) {
        int i = tid + 256 * s;
        int r = i >> 3, c8 = (i & 7) * 8;
        uint32_t off = (uint32_t)(r * GS + c8) * 2;
        cpa16(sA + off, a + r * Dn + c8);
        cpa16(sW + off, b + r * Dn + c8);
    }
    CP_COMMIT();
}

__device__ __forceinline__ void gemm_pipe(
    const __half* __restrict__ Ag, const __half* __restrict__ Bg,
    uint32_t smBase, int lane, int wm, int wn, int tid, float acc[2][8][4])
{
    const int lrow = lane & 15;
    const int lcol = (lane >> 4) << 3;
    const int r0w  = wm * 32;
    const int nbw  = wn * 64;
    const int NT   = Dn / 64;

    gemm_fill(Ag, Bg, smBase, 0, 0, tid);
    gemm_fill(Ag, Bg, smBase, 1, 1, tid);

    int comp_stage = 0, fill_stage = 2;
    for (int kt = 0; kt < NT; kt++) {
        if (kt + 1 < NT) CP_WAIT(1); else CP_WAIT(0);
        __syncthreads();                       // single barrier per tile
        if (kt + 2 < NT) {
            gemm_fill(Ag, Bg, smBase, kt + 2, fill_stage, tid);
            if (++fill_stage == 3) fill_stage = 0;
        }

        const uint32_t sA = smBase + comp_stage * GEMM_STAGE_STRIDE;
        const uint32_t sW = sA + STG_BYTES;
        if (++comp_stage == 3) comp_stage = 0;

        #pragma unroll
        for (int ks = 0; ks < 4; ks++) {
            unsigned a[2][4];
            #pragma unroll
            for (int mt = 0; mt < 2; mt++)
                ldsm4(a[mt][0], a[mt][1], a[mt][2], a[mt][3],
                      sA + ((r0w + mt * 16 + lrow) * GS + ks * 16 + lcol) * 2);
            #pragma unroll
            for (int jj = 0; jj < 4; jj++) {
                unsigned b0, b1, b2, b3;
                ldsm4(b0, b1, b2, b3,
                      sW + ((nbw + jj * 16 + lrow) * GS + ks * 16 + lcol) * 2);
                #pragma unroll
                for (int mt = 0; mt < 2; mt++) {
                    mma_f16(acc[mt][2 * jj],     a[mt], b0, b2);
                    mma_f16(acc[mt][2 * jj + 1], a[mt], b1, b3);
                }
            }
        }
    }
}

// ---------------------------------------------------------------------------
// Kernel 1: QKV = x @ w_qkv^T + b_qkv, fused RoPE; q scaled by (1/8)*log2(e)
// ---------------------------------------------------------------------------
__global__ __launch_bounds__(256, 2) void qkv_mma_kernel(
    const float* __restrict__ bias, const float* __restrict__ fc,
    const float* __restrict__ fs)
{
    extern __shared__ __half dynsm[];
    const uint32_t smBase = (uint32_t)__cvta_generic_to_shared(dynsm);
    const int tid  = threadIdx.x;
    const int warp = tid >> 5, lane = tid & 31;
    const int wm = warp & 3, wn = warp >> 2;
    const int m0 = blockIdx.y * 128;
    const int n0 = blockIdx.x * 128;

    float acc[2][8][4];
    #pragma unroll
    for (int mt = 0; mt < 2; mt++)
        #pragma unroll
        for (int j = 0; j < 8; j++)
            #pragma unroll
            for (int e = 0; e < 4; e++) acc[mt][j][e] = 0.f;

    gemm_pipe(g_x16 + m0 * Dn, g_wq16 + n0 * Dn, smBase, lane, wm, wn, tid, acc);

    const int region = n0 >> 10;
    __half* dst = (region == 0) ? g_Q : (region == 1) ? g_K : g_V;
    const int rbase = m0 + wm * 32 + (lane >> 2);

    #pragma unroll
    for (int j = 0; j < 8; j++) {
        const int n  = n0 + wn * 64 + j * 8 + (lane & 3) * 2;
        const int h  = (n & 1023) >> 6;
        const int d  = n & 63;
        const int p  = d >> 1;
        const float bv0 = bias[n], bv1 = bias[n + 1];
        #pragma unroll
        for (int mt = 0; mt < 2; mt++) {
            #pragma unroll
            for (int half = 0; half < 2; half++) {
                const int r  = rbase + mt * 16 + half * 8;
                const int bi = r >> 11;
                const int t  = r & 2047;
                float re = acc[mt][j][half * 2 + 0] + bv0;
                float im = acc[mt][j][half * 2 + 1] + bv1;
                if (region < 2) {
                    float c = fc[t * (DKn / 2) + p];
                    float s = fs[t * (DKn / 2) + p];
                    float nre = re * c - im * s;
                    float nim = re * s + im * c;
                    re = nre; im = nim;
                    if (region == 0) { re *= QSCALE; im *= QSCALE; }
                }
                *(unsigned*)&dst[((bi * Hn + h) * Tn + t) * DKn + d] =
                    pack_h2(re, im);
            }
        }
    }
}

// ---------------------------------------------------------------------------
// Kernel 3: out = g_A @ w_out^T + b_out (fp32 output)
// ---------------------------------------------------------------------------
__global__ __launch_bounds__(256, 2) void proj_mma_kernel(
    const float* __restrict__ bias, float* __restrict__ out)
{
    extern __shared__ __half dynsm[];
    const uint32_t smBase = (uint32_t)__cvta_generic_to_shared(dynsm);
    const int tid  = threadIdx.x;
    const int warp = tid >> 5, lane = tid & 31;
    const int wm = warp & 3, wn = warp >> 2;
    const int m0 = blockIdx.y * 128;
    const int n0 = blockIdx.x * 128;

    float acc[2][8][4];
    #pragma unroll
    for (int mt = 0; mt < 2; mt++)
        #pragma unroll
        for (int j = 0; j < 8; j++)
            #pragma unroll
            for (int e = 0; e < 4; e++) acc[mt][j][e] = 0.f;

    gemm_pipe(g_A + m0 * Dn, g_wo16 + n0 * Dn, smBase, lane, wm, wn, tid, acc);

    const int rbase = m0 + wm * 32 + (lane >> 2);
    #pragma unroll
    for (int j = 0; j < 8; j++) {
        const int n = n0 + wn * 64 + j * 8 + (lane & 3) * 2;
        const float bv0 = bias[n], bv1 = bias[n + 1];
        #pragma unroll
        for (int mt = 0; mt < 2; mt++) {
            #pragma unroll
            for (int half = 0; half < 2; half++) {
                const int r = rbase + mt * 16 + half * 8;
                *(float2*)&out[r * Dn + n] =
                    make_float2(acc[mt][j][half * 2 + 0] + bv0,
                                acc[mt][j][half * 2 + 1] + bv1);
            }
        }
    }
}

// ---------------------------------------------------------------------------
// Kernel 2: causal flash attention, fp16 mma, 3-stage cp.async KV ring,
// one barrier per tile. exp2-domain softmax (scores already x log2e).
// ---------------------------------------------------------------------------
#define KSTG_BYTES (64 * GS * 2)                  // 9216 B (K or V stage half)
#define ATT_STAGE_STRIDE (2 * KSTG_BYTES)         // 18432 B
#define ATT_SM_BYTES (3 * ATT_STAGE_STRIDE)       // 55296 B

__device__ __forceinline__ void attn_fill(
    const __half* __restrict__ Kg, const __half* __restrict__ Vg,
    uint32_t smBase, int kt, int stage, int tid)
{
    const int k0 = kt * 64;
    const uint32_t sK = smBase + stage * ATT_STAGE_STRIDE;
    const uint32_t sV = sK + KSTG_BYTES;
    #pragma unroll
    for (int s = 0; s < 2; s++) {
        int i = tid + 256 * s;
        int r = i >> 3, c8 = (i & 7) * 8;
        uint32_t off = (uint32_t)(r * GS + c8) * 2;
        cpa16(sK + off, Kg + (k0 + r) * DKn + c8);
        cpa16(sV + off, Vg + (k0 + r) * DKn + c8);
    }
    CP_COMMIT();
}

__global__ __launch_bounds__(256, 2) void attn_mma_kernel()
{
    extern __shared__ __half dynsm[];
    const uint32_t smBase = (uint32_t)__cvta_generic_to_shared(dynsm);

    const int tid  = threadIdx.x;
    const int warp = tid >> 5, lane = tid & 31;
    const int q    = lane >> 2, l3 = lane & 3;
    const int lrow = lane & 15;
    const int lcol = (lane >> 4) << 3;
    const int qblk = (int)gridDim.x - 1 - (int)blockIdx.x;
    const int bh   = blockIdx.y;
    const int q0   = qblk * 128;

    const __half* Qg = g_Q + (bh * Tn + q0) * DKn;
    const __half* Kg = g_K + bh * Tn * DKn;
    const __half* Vg = g_V + bh * Tn * DKn;

    // Stage Q in smem (aliases KV ring), pull fragments, release.
    #pragma unroll
    for (int s = 0; s < 4; s++) {
        int idx = tid + 256 * s;
        int r = idx >> 3, c8 = (idx & 7) * 8;
        *(uint4*)&dynsm[r * GS + c8] = *(const uint4*)&Qg[r * DKn + c8];
    }
    __syncthreads();

    const int wrow = warp * 16;
    unsigned Qf[4][4];
    #pragma unroll
    for (int ks = 0; ks < 4; ks++)
        ldsm4(Qf[ks][0], Qf[ks][1], Qf[ks][2], Qf[ks][3],
              smBase + ((wrow + lrow) * GS + ks * 16 + lcol) * 2);
    __syncthreads();   // Q reads done before KV fills overwrite

    float O[8][4];
    #pragma unroll
    for (int j = 0; j < 8; j++)
        #pragma unroll
        for (int e = 0; e < 4; e++) O[j][e] = 0.f;
    float m_lo = -1e30f, m_hi = -1e30f, l_lo = 0.f, l_hi = 0.f;

    const int wr_lo = q0 + wrow;
    const int wr_hi = wr_lo + 15;
    const int n_kt  = 2 * qblk + 2;

    attn_fill(Kg, Vg, smBase, 0, 0, tid);
    if (n_kt > 1) attn_fill(Kg, Vg, smBase, 1, 1, tid);

    int comp_stage = 0, fill_stage = 2;
    for (int kt = 0; kt < n_kt; kt++) {
        if (kt + 1 < n_kt) CP_WAIT(1); else CP_WAIT(0);
        __syncthreads();                      // single barrier per tile
        if (kt + 2 < n_kt) {
            attn_fill(Kg, Vg, smBase, kt + 2, fill_stage, tid);
            if (++fill_stage == 3) fill_stage = 0;
        }
        const uint32_t sK = smBase + comp_stage * ATT_STAGE_STRIDE;
        const uint32_t sV = sK + KSTG_BYTES;
        if (++comp_stage == 3) comp_stage = 0;

        const int k0 = kt * 64;
        if (k0 > wr_hi) continue;             // fully masked for this warp

        float S[8][4];
        #pragma unroll
        for (int j = 0; j < 8; j++)
            #pragma unroll
            for (int e = 0; e < 4; e++) S[j][e] = 0.f;

        #pragma unroll
        for (int ks = 0; ks < 4; ks++) {
            #pragma unroll
            for (int jj = 0; jj < 4; jj++) {
                unsigned b0, b1, b2, b3;
                ldsm4(b0, b1, b2, b3,
                      sK + ((jj * 16 + lrow) * GS + ks * 16 + lcol) * 2);
                mma_f16(S[2 * jj],     Qf[ks], b0, b2);
                mma_f16(S[2 * jj + 1], Qf[ks], b1, b3);
            }
        }

        if (k0 + 63 > wr_lo) {
            const int r0 = wr_lo + q;
            #pragma unroll
            for (int j = 0; j < 8; j++) {
                const int c = k0 + j * 8 + 2 * l3;
                if (c     > r0)     S[j][0] = -1e30f;
                if (c + 1 > r0)     S[j][1] = -1e30f;
                if (c     > r0 + 8) S[j][2] = -1e30f;
                if (c + 1 > r0 + 8) S[j][3] = -1e30f;
            }
        }

        float mx0 = -1e30f, mx1 = -1e30f;
        #pragma unroll
        for (int j = 0; j < 8; j++) {
            mx0 = fmaxf(mx0, fmaxf(S[j][0], S[j][1]));
            mx1 = fmaxf(mx1, fmaxf(S[j][2], S[j][3]));
        }
        mx0 = fmaxf(mx0, __shfl_xor_sync(0xffffffffu, mx0, 1));
        mx0 = fmaxf(mx0, __shfl_xor_sync(0xffffffffu, mx0, 2));
        mx1 = fmaxf(mx1, __shfl_xor_sync(0xffffffffu, mx1, 1));
        mx1 = fmaxf(mx1, __shfl_xor_sync(0xffffffffu, mx1, 2));

        const float mn0 = fmaxf(m_lo, mx0);
        const float mn1 = fmaxf(m_hi, mx1);
        const float a0  = fex2(m_lo - mn0);   // log2-domain
        const float a1  = fex2(m_hi - mn1);
        m_lo = mn0; m_hi = mn1;

        float s0 = 0.f, s1 = 0.f;
        #pragma unroll
        for (int j = 0; j < 8; j++) {
            S[j][0] = fex2(S[j][0] - mn0);
            S[j][1] = fex2(S[j][1] - mn0);
            s0 += S[j][0] + S[j][1];
            S[j][2] = fex2(S[j][2] - mn1);
            S[j][3] = fex2(S[j][3] - mn1);
            s1 += S[j][2] + S[j][3];
        }
        s0 += __shfl_xor_sync(0xffffffffu, s0, 1);
        s0 += __shfl_xor_sync(0xffffffffu, s0, 2);
        s1 += __shfl_xor_sync(0xffffffffu, s1, 1);
        s1 += __shfl_xor_sync(0xffffffffu, s1, 2);
        l_lo = l_lo * a0 + s0;
        l_hi = l_hi * a1 + s1;

        #pragma unroll
        for (int j = 0; j < 8; j++) {
            O[j][0] *= a0; O[j][1] *= a0;
            O[j][2] *= a1; O[j][3] *= a1;
        }

        #pragma unroll
        for (int ksp = 0; ksp < 4; ksp++) {
            unsigned A[4];
            A[0] = pack_h2(S[2 * ksp][0],     S[2 * ksp][1]);
            A[1] = pack_h2(S[2 * ksp][2],     S[2 * ksp][3]);
            A[2] = pack_h2(S[2 * ksp + 1][0], S[2 * ksp + 1][1]);
            A[3] = pack_h2(S[2 * ksp + 1][2], S[2 * ksp + 1][3]);
            #pragma unroll
            for (int dd = 0; dd < 4; dd++) {
                unsigned b0, b1, b2, b3;
                ldsm4t(b0, b1, b2, b3,
                       sV + ((ksp * 16 + lrow) * GS + dd * 16 + lcol) * 2);
                mma_f16(O[2 * dd],     A, b0, b1);
                mma_f16(O[2 * dd + 1], A, b2, b3);
            }
        }
    }

    const int bi = bh >> 4;
    const int h  = bh & 15;
    const float inv0 = 1.f / l_lo;
    const float inv1 = 1.f / l_hi;
    const int t0 = q0 + wrow + q;
    __half* outp = g_A + (bi * Tn + t0) * Dn + h * DKn;
    #pragma unroll
    for (int j = 0; j < 8; j++) {
        *(unsigned*)&outp[j * 8 + 2 * l3] =
            pack_h2(O[j][0] * inv0, O[j][1] * inv0);
        *(unsigned*)&outp[8 * Dn + j * 8 + 2 * l3] =
            pack_h2(O[j][2] * inv1, O[j][3] * inv1);
    }
}

// ---------------------------------------------------------------------------
extern "C" void kernel_launch(void* const* d_in, const int* in_sizes, int n_in,
                              void* d_out, int out_size)
{
    const float* x    = (const float*)d_in[0];
    const float* wqkv = (const float*)d_in[1];
    const float* bqkv = (const float*)d_in[2];
    const float* wout = (const float*)d_in[3];
    const float* bout = (const float*)d_in[4];
    const float* fc   = (const float*)d_in[5];
    const float* fs   = (const float*)d_in[6];
    float* out = (float*)d_out;

    __half* dx;  cudaGetSymbolAddress((void**)&dx,  g_x16);
    __half* dwq; cudaGetSymbolAddress((void**)&dwq, g_wq16);
    __half* dwo; cudaGetSymbolAddress((void**)&dwo, g_wo16);

    cudaFuncSetAttribute(qkv_mma_kernel,
                         cudaFuncAttributeMaxDynamicSharedMemorySize,
                         GEMM_SM_BYTES);
    cudaFuncSetAttribute(proj_mma_kernel,
                         cudaFuncAttributeMaxDynamicSharedMemorySize,
                         GEMM_SM_BYTES);
    cudaFuncSetAttribute(attn_mma_kernel,
                         cudaFuncAttributeMaxDynamicSharedMemorySize,
                         ATT_SM_BYTES);

    f2h_kernel<<<Mn * Dn / 2048, 256>>>(x, dx);
    f2h_kernel<<<Nqkv * Dn / 2048, 256>>>(wqkv, dwq);
    f2h_kernel<<<Dn * Dn / 2048, 256>>>(wout, dwo);

    qkv_mma_kernel<<<dim3(Nqkv / 128, Mn / 128), 256, GEMM_SM_BYTES>>>(bqkv, fc, fs);
    attn_mma_kernel<<<dim3(Tn / 128, Bn * Hn), 256, ATT_SM_BYTES>>>();
    proj_mma_kernel<<<dim3(Dn / 128, Mn / 128), 256, GEMM_SM_BYTES>>>(bout, out);
}